// round 15
// baseline (speedup 1.0000x reference)
#include <cuda_runtime.h>
#include <cuda_fp16.h>
#include <cstdint>

// ---------------- problem constants ----------------
#define BSZ  4
#define SEQ  2048
#define CH   768
#define NH   12
#define HD   64
#define BHN  (BSZ*NH)          // 48

// ---------------- tiled fp16 scratch (uint32 = half2) ----------------
__device__ __align__(16) uint32_t g_xt [(size_t)64*24*2176];   // x   [mblk][chunk32]
__device__ __align__(16) uint32_t g_wqt[(size_t)18*24*2176];   // w_qkv
__device__ __align__(16) uint32_t g_wpt[(size_t) 6*24*2176];   // w_proj
__device__ __align__(16) uint32_t g_ot [(size_t)64*24*2176];   // attn out
__device__ __align__(16) uint32_t g_qt [(size_t)BHN*16*4352];  // Q: 128-tok blk (RS272)
__device__ __align__(16) uint32_t g_kt [(size_t)BHN*32*2304];  // K: 64-tok blk  (RS144)
__device__ __align__(16) uint32_t g_vt [(size_t)BHN*32*2304];  // V: 64-tok blk  (RS144)

// ---------------- helpers ----------------
__device__ __forceinline__ uint32_t fsw(uint32_t x) { return x ^ (x >> 2); }

__device__ __forceinline__ uint32_t pack2(float lo, float hi) {   // lo -> bits[0:16)
    uint32_t r; asm("cvt.rn.f16x2.f32 %0, %1, %2;" : "=r"(r) : "f"(hi), "f"(lo));
    return r;
}
__device__ __forceinline__ float ex2f(float x) {
    float y; asm("ex2.approx.f32 %0, %1;" : "=f"(y) : "f"(x)); return y;
}
__device__ __forceinline__ uint32_t s2u(const void* p) {
    uint32_t a;
    asm("{ .reg .u64 t; cvta.to.shared.u64 t, %1; cvt.u32.u64 %0, t; }"
        : "=r"(a) : "l"(p));
    return a;
}
__device__ __forceinline__ void cp16(uint32_t dst, const void* src) {
    asm volatile("cp.async.cg.shared.global [%0], [%1], 16;"
                 :: "r"(dst), "l"(src) : "memory");
}
#define CP_COMMIT() asm volatile("cp.async.commit_group;" ::: "memory")
#define CP_WAIT0()  asm volatile("cp.async.wait_group 0;" ::: "memory")
#define CP_WAIT1()  asm volatile("cp.async.wait_group 1;" ::: "memory")

// D += A(16x16,row,f16) * B(16x8,col,f16), fp32 accum
__device__ __forceinline__ void mma16(float* c, const uint32_t* a, const uint32_t* b) {
    asm("mma.sync.aligned.m16n8k16.row.col.f32.f16.f16.f32 "
        "{%0,%1,%2,%3}, {%4,%5,%6,%7}, {%8,%9}, {%0,%1,%2,%3};"
        : "+f"(c[0]), "+f"(c[1]), "+f"(c[2]), "+f"(c[3])
        : "r"(a[0]), "r"(a[1]), "r"(a[2]), "r"(a[3]), "r"(b[0]), "r"(b[1]));
}
__device__ __forceinline__ float fidx(const float4& v, int s) {
    return (s == 0) ? v.x : (s == 1) ? v.y : (s == 2) ? v.z : v.w;
}

// PT word offsets: q = (kw>>3)*4 + (kw&3), e = (kw>>2)&1
__device__ __forceinline__ uint32_t offh(int kw, int col) {   // RS272 (128 cols)
    return (uint32_t)((((kw >> 3) * 4 + (kw & 3)) * 272
                      + 2 * fsw((uint32_t)(col ^ ((kw & 3) << 2))) + ((kw >> 2) & 1)));
}
__device__ __forceinline__ uint32_t off64(int kw, int col) {  // RS144 (64 cols)
    return (uint32_t)((((kw >> 3) * 4 + (kw & 3)) * 144
                      + 2 * fsw((uint32_t)(col ^ ((kw & 3) << 2))) + ((kw >> 2) & 1)));
}

// =====================================================================
// Prep: x, w_qkv, w_proj -> fp16 PT tiles
// =====================================================================
__global__ void prep_all(const float* __restrict__ x,
                         const float* __restrict__ wq,
                         const float* __restrict__ wp)
{
    const int blk = blockIdx.x;
    if (blk < 6144) {
        const int idx = blk * 256 + threadIdx.x;
        const int m  = idx / 192;
        const int k4 = (idx - m * 192) * 4;
        const float4 v = *(const float4*)(x + (size_t)m * CH + k4);
        uint32_t* tile = g_xt + ((size_t)(m >> 7) * 24 + (k4 >> 5)) * 2176;
        const int ml = m & 127;
        const int kwl = (k4 & 31) >> 1;
        tile[offh(kwl,     ml)] = pack2(v.x, v.y);
        tile[offh(kwl + 1, ml)] = pack2(v.z, v.w);
    } else if (blk < 6144 + 864) {
        const int idx = (blk - 6144) * 256 + threadIdx.x;
        const int N = 3 * CH, NPR = N / 4;
        const int kp = idx / NPR;
        const int n4 = (idx - kp * NPR) * 4;
        const float4 v0 = *(const float4*)(wq + (size_t)(2 * kp)     * N + n4);
        const float4 v1 = *(const float4*)(wq + (size_t)(2 * kp + 1) * N + n4);
        uint32_t* tile = g_wqt + ((size_t)(n4 >> 7) * 24 + (kp >> 4)) * 2176;
        const int kwl = kp & 15, nl = n4 & 127;
#pragma unroll
        for (int s = 0; s < 4; ++s)
            tile[offh(kwl, nl + s)] = pack2(fidx(v0, s), fidx(v1, s));
    } else {
        const int idx = (blk - 6144 - 864) * 256 + threadIdx.x;
        const int N = CH, NPR = N / 4;
        const int kp = idx / NPR;
        const int n4 = (idx - kp * NPR) * 4;
        const float4 v0 = *(const float4*)(wp + (size_t)(2 * kp)     * N + n4);
        const float4 v1 = *(const float4*)(wp + (size_t)(2 * kp + 1) * N + n4);
        uint32_t* tile = g_wpt + ((size_t)(n4 >> 7) * 24 + (kp >> 4)) * 2176;
        const int kwl = kp & 15, nl = n4 & 127;
#pragma unroll
        for (int s = 0; s < 4; ++s)
            tile[offh(kwl, nl + s)] = pack2(fidx(v0, s), fidx(v1, s));
    }
}

// =====================================================================
// GEMM core: 128x128 CTA, 8 warps (warp 32x64), fp16, K-chunk 64,
// 3 stages (104448 B smem) — unchanged.
// =====================================================================
__device__ __forceinline__ void gemm_core(const uint32_t* __restrict__ gA,
                                          const uint32_t* __restrict__ gB,
                                          float acc[2][8][4])
{
    extern __shared__ __align__(16) uint32_t smw[];
    const uint32_t sb = s2u(smw);

    const int tid = threadIdx.x;
    const int lane = tid & 31, wid = tid >> 5;
    const int g = lane >> 2, t = lane & 3;
    const int wm = (wid >> 1) * 32, wn = (wid & 1) * 64;

    uint32_t aFr[2][2], bFr[8];
#pragma unroll
    for (int mt = 0; mt < 2; ++mt)
#pragma unroll
        for (int h = 0; h < 2; ++h)
            aFr[mt][h] = (uint32_t)(t * 272
                        + 2 * fsw((uint32_t)((wm + mt * 16 + g + 8 * h) ^ (t << 2))));
#pragma unroll
    for (int nt = 0; nt < 8; ++nt)
        bFr[nt] = (uint32_t)(4352 + t * 272
                 + 2 * fsw((uint32_t)((wn + nt * 8 + g) ^ (t << 2))));

#pragma unroll
    for (int mt = 0; mt < 2; ++mt)
#pragma unroll
        for (int nt = 0; nt < 8; ++nt)
#pragma unroll
            for (int j = 0; j < 4; ++j) acc[mt][nt][j] = 0.f;

    auto copy = [&](int c, int stg) {
        const uint32_t d0 = sb + (uint32_t)stg * 34816u;
        const uint32_t* sA = gA + (size_t)c * 4352;
        const uint32_t* sB = gB + (size_t)c * 4352;
#pragma unroll
        for (int rep = 0; rep < 9; ++rep) {
            const int i = tid + rep * 256;
            if (i < 2176) {
                const uint32_t* src = (i < 1088) ? (sA + i * 4) : (sB + (i - 1088) * 4);
                cp16(d0 + (uint32_t)i * 16u, src);
            }
        }
    };
    auto compute = [&](const uint32_t* st) {
#pragma unroll
        for (int ks = 0; ks < 4; ++ks) {
            uint2 aw00 = *(const uint2*)&st[ks * 1088 + aFr[0][0]];
            uint2 aw01 = *(const uint2*)&st[ks * 1088 + aFr[0][1]];
            uint2 aw10 = *(const uint2*)&st[ks * 1088 + aFr[1][0]];
            uint2 aw11 = *(const uint2*)&st[ks * 1088 + aFr[1][1]];
            uint32_t a0[4] = {aw00.x, aw01.x, aw00.y, aw01.y};
            uint32_t a1[4] = {aw10.x, aw11.x, aw10.y, aw11.y};
#pragma unroll
            for (int nt = 0; nt < 8; ++nt) {
                uint2 bw = *(const uint2*)&st[ks * 1088 + bFr[nt]];
                uint32_t b[2] = {bw.x, bw.y};
                mma16(acc[0][nt], a0, b);
                mma16(acc[1][nt], a1, b);
            }
        }
    };

    copy(0, 0); CP_COMMIT();
    copy(1, 1); CP_COMMIT();

    for (int c = 0; c < 12; c += 3) {
        CP_WAIT1(); __syncthreads();
        if (c + 2 < 12) copy(c + 2, 2);
        CP_COMMIT();
        compute(smw);

        CP_WAIT1(); __syncthreads();
        if (c + 3 < 12) copy(c + 3, 0);
        CP_COMMIT();
        compute(smw + 8704);

        CP_WAIT1(); __syncthreads();
        if (c + 4 < 12) copy(c + 4, 1);
        CP_COMMIT();
        compute(smw + 17408);
    }
}

// =====================================================================
// GEMM 1: qkv; scatters fp16 tiles. Q pre-scaled by 0.125*log2(e).
// =====================================================================
__global__ __launch_bounds__(256, 2) void qkv_mma()
{
    float acc[2][8][4];
    const uint32_t* gA = g_xt  + (size_t)blockIdx.y * 24 * 2176;
    const uint32_t* gB = g_wqt + (size_t)blockIdx.x * 24 * 2176;
    gemm_core(gA, gB, acc);

    const int tid = threadIdx.x;
    const int lane = tid & 31, wid = tid >> 5;
    const int g = lane >> 2, t = lane & 3;
    const int wm = (wid >> 1) * 32, wn = (wid & 1) * 64;
    const int m0 = blockIdx.y * 128;

    const int t3 = blockIdx.x / 6;
    const int nb = (blockIdx.x % 6) * 128;
    const float qs = 0.125f * 1.44269504f;

#pragma unroll
    for (int mt = 0; mt < 2; ++mt) {
        const int r = m0 + wm + mt * 16 + g;
        const int b = r >> 11, n = r & (SEQ - 1);
#pragma unroll
        for (int nt = 0; nt < 8; ++nt) {
            const int cb = nb + wn + nt * 8 + 2 * t;     // even
            const int h = cb >> 6, d = cb & 63;
            if (t3 == 0) {
                const size_t tb = (size_t)(b * NH + h) * 16 + (n >> 7);
                uint32_t* tile = g_qt + tb * 4352;
                const int nl = n & 127;
                tile[offh(d >> 1, nl    )] = pack2(acc[mt][nt][0] * qs,
                                                   acc[mt][nt][1] * qs);
                tile[offh(d >> 1, nl + 8)] = pack2(acc[mt][nt][2] * qs,
                                                   acc[mt][nt][3] * qs);
            } else if (t3 == 1) {
                const size_t tb = (size_t)(b * NH + h) * 32 + (n >> 6);
                uint32_t* tile = g_kt + tb * 2304;
                const int nl = n & 63;
                tile[off64(d >> 1, nl    )] = pack2(acc[mt][nt][0], acc[mt][nt][1]);
                tile[off64(d >> 1, nl + 8)] = pack2(acc[mt][nt][2], acc[mt][nt][3]);
            } else {
                const size_t tb = (size_t)(b * NH + h) * 32 + (n >> 6);
                __half* vt = (__half*)(g_vt + tb * 2304);
                const int nl = n & 63;
                const int kwl = nl >> 1, par = nl & 1;
                vt[off64(kwl,     d    ) * 2 + par] = __float2half_rn(acc[mt][nt][0]);
                vt[off64(kwl,     d + 1) * 2 + par] = __float2half_rn(acc[mt][nt][1]);
                vt[off64(kwl + 4, d    ) * 2 + par] = __float2half_rn(acc[mt][nt][2]);
                vt[off64(kwl + 4, d + 1) * 2 + par] = __float2half_rn(acc[mt][nt][3]);
            }
        }
    }
}

// =====================================================================
// GEMM 2: out = o @ w_proj + bias (fp32 out)
// =====================================================================
__global__ __launch_bounds__(256, 2) void proj_mma(const float* __restrict__ bias,
                                                   float* __restrict__ out)
{
    float acc[2][8][4];
    const uint32_t* gA = g_ot  + (size_t)blockIdx.y * 24 * 2176;
    const uint32_t* gB = g_wpt + (size_t)blockIdx.x * 24 * 2176;
    gemm_core(gA, gB, acc);

    const int tid = threadIdx.x;
    const int lane = tid & 31, wid = tid >> 5;
    const int g = lane >> 2, t = lane & 3;
    const int wm = (wid >> 1) * 32, wn = (wid & 1) * 64;
    const int m0 = blockIdx.y * 128, n0 = blockIdx.x * 128;

#pragma unroll
    for (int mt = 0; mt < 2; ++mt) {
        const int r = m0 + wm + mt * 16 + g;
#pragma unroll
        for (int nt = 0; nt < 8; ++nt) {
            const int col = n0 + wn + nt * 8 + 2 * t;
            const float2 bv = *(const float2*)(bias + col);
            float* p = out + (size_t)r * CH + col;
            *(float2*)p = make_float2(acc[mt][nt][0] + bv.x, acc[mt][nt][1] + bv.y);
            *(float2*)(p + 8 * CH) = make_float2(acc[mt][nt][2] + bv.x,
                                                 acc[mt][nt][3] + bv.y);
        }
    }
}

// =====================================================================
// Flash attention (fp16): 128-wide KV tiles, ONE sync per tile.
// Inner work decomposed into 8 independent 16-kv GROUPS per tile
// (S-mma 8 HMMA -> ex2 8 -> pack -> PV 8 HMMA), group-local score
// registers so tensor and MUFU phases of adjacent groups overlap.
// smem: [K(2x2304) | V(2x2304)] x2 buf = 73728 B -> 2 CTAs/SM.
// =====================================================================
__global__ __launch_bounds__(256, 2) void attn_mma()
{
    extern __shared__ __align__(16) uint32_t sm[];
    const uint32_t sb = s2u(sm);

    const int bh = blockIdx.y;
    const int it = (gridDim.x - 1) - blockIdx.x;   // longest first
    const int r0 = it * 128;
    const int njt = it + 1;                        // 128-wide tiles

    const int tid  = threadIdx.x;
    const int lane = tid & 31;
    const int wid  = tid >> 5;
    const int g    = lane >> 2;
    const int t    = lane & 3;
    const int wm   = wid * 16;

    // ---- fragment offsets (same pattern for K and V 64-blocks) ----
    uint32_t bF[8];
#pragma unroll
    for (int nt = 0; nt < 8; ++nt)
        bF[nt] = t * 144 + 2 * fsw((uint32_t)((nt * 8 + g) ^ (t << 2)));

    // ---- Q fragments into registers ----
    const uint32_t* Qg = g_qt + ((size_t)bh * 16 + it) * 4352;
    uint32_t qa[4][4];
    {
        uint32_t qoff0 = t * 272 + 2 * fsw((uint32_t)((wm + g) ^ (t << 2)));
        uint32_t qoff1 = t * 272 + 2 * fsw((uint32_t)((wm + g + 8) ^ (t << 2)));
#pragma unroll
        for (int ks = 0; ks < 4; ++ks) {
            const uint2 aw0 = *(const uint2*)(Qg + ks * 1088 + qoff0);
            const uint2 aw1 = *(const uint2*)(Qg + ks * 1088 + qoff1);
            qa[ks][0] = aw0.x; qa[ks][1] = aw1.x;
            qa[ks][2] = aw0.y; qa[ks][3] = aw1.y;
        }
    }

    const uint32_t* kbase = g_kt + (size_t)bh * 32 * 2304;
    const uint32_t* vbase = g_vt + (size_t)bh * 32 * 2304;

    auto copyKV = [&](int j, int buf) {
        const uint32_t* sK = kbase + (size_t)(2 * j) * 2304;
        const uint32_t* sV = vbase + (size_t)(2 * j) * 2304;
        const uint32_t dK = sb + (uint32_t)buf * 36864u;
        const uint32_t dV = dK + 18432u;
#pragma unroll
        for (int rep = 0; rep < 5; ++rep) {
            const int i = tid + rep * 256;
            if (i < 1152) cp16(dK + (uint32_t)i * 16u, sK + i * 4);
        }
#pragma unroll
        for (int rep = 0; rep < 5; ++rep) {
            const int i = tid + rep * 256;
            if (i < 1152) cp16(dV + (uint32_t)i * 16u, sV + i * 4);
        }
    };

    copyKV(0, 0); CP_COMMIT();

    float o[8][4];
    float l0 = 0.f, l1 = 0.f;     // per-lane partial row sums
#pragma unroll
    for (int nt = 0; nt < 8; ++nt)
        o[nt][0] = o[nt][1] = o[nt][2] = o[nt][3] = 0.f;

    for (int jt = 0; jt < njt; ++jt) {
        CP_WAIT0();
        __syncthreads();

        if (jt + 1 < njt) { copyKV(jt + 1, (jt + 1) & 1); CP_COMMIT(); }

        const uint32_t* Tb = sm + (uint32_t)(jt & 1) * 9216;
        const bool diag = (jt == njt - 1);
        const int rg0 = r0 + wm + g, rg1 = rg0 + 8;

        // ---- 8 independent 16-kv groups (2 halves x 4) ----
#pragma unroll
        for (int grp = 0; grp < 8; ++grp) {
            const int hf = grp >> 2;            // kv half 0/1
            const int gq = grp & 3;             // 16-kv block within half
            const uint32_t* Kt = Tb + hf * 2304;
            const uint32_t* Vt = Tb + 4608 + hf * 2304;

            // S-mma: 2 nt columns (nt = 2gq, 2gq+1), all 4 ks
            float s0[4] = {0.f, 0.f, 0.f, 0.f};
            float s1[4] = {0.f, 0.f, 0.f, 0.f};
#pragma unroll
            for (int ks = 0; ks < 4; ++ks) {
                uint2 bw0 = *(const uint2*)&Kt[ks * 576 + bF[2 * gq]];
                uint2 bw1 = *(const uint2*)&Kt[ks * 576 + bF[2 * gq + 1]];
                uint32_t b0[2] = {bw0.x, bw0.y};
                uint32_t b1[2] = {bw1.x, bw1.y};
                mma16(s0, qa[ks], b0);
                mma16(s1, qa[ks], b1);
            }

            // causal mask (diag tile only)
            if (diag) {
                const int c0 = jt * 128 + hf * 64 + gq * 16;
                const int cg0 = c0 + 2 * t;          // nt = 2gq
                const int cg1 = c0 + 8 + 2 * t;      // nt = 2gq+1
                if (cg0     > rg0) s0[0] = -1e30f;
                if (cg0 + 1 > rg0) s0[1] = -1e30f;
                if (cg0     > rg1) s0[2] = -1e30f;
                if (cg0 + 1 > rg1) s0[3] = -1e30f;
                if (cg1     > rg0) s1[0] = -1e30f;
                if (cg1 + 1 > rg0) s1[1] = -1e30f;
                if (cg1     > rg1) s1[2] = -1e30f;
                if (cg1 + 1 > rg1) s1[3] = -1e30f;
            }

            // ex2 + row-sum partials
            s0[0] = ex2f(s0[0]); s0[1] = ex2f(s0[1]);
            s0[2] = ex2f(s0[2]); s0[3] = ex2f(s0[3]);
            s1[0] = ex2f(s1[0]); s1[1] = ex2f(s1[1]);
            s1[2] = ex2f(s1[2]); s1[3] = ex2f(s1[3]);
            l0 += s0[0] + s0[1] + s1[0] + s1[1];
            l1 += s0[2] + s0[3] + s1[2] + s1[3];

            // pack to PV A-fragment and accumulate
            uint32_t a[4];
            a[0] = pack2(s0[0], s0[1]);
            a[1] = pack2(s0[2], s0[3]);
            a[2] = pack2(s1[0], s1[1]);
            a[3] = pack2(s1[2], s1[3]);
#pragma unroll
            for (int nt = 0; nt < 8; ++nt) {
                uint2 bw = *(const uint2*)&Vt[gq * 576 + bF[nt]];
                uint32_t b[2] = {bw.x, bw.y};
                mma16(o[nt], a, b);
            }
        }
    }

    // ---- final row-sum reduction over the t-quad ----
    l0 += __shfl_xor_sync(0xffffffffu, l0, 1);
    l0 += __shfl_xor_sync(0xffffffffu, l0, 2);
    l1 += __shfl_xor_sync(0xffffffffu, l1, 1);
    l1 += __shfl_xor_sync(0xffffffffu, l1, 2);

    // ---- normalize + write fp16 PT-A tiles for proj ----
    const int b = bh / NH, h = bh % NH;
    const float inv0 = 1.0f / l0, inv1 = 1.0f / l1;
    const int mblk = (int)(((size_t)b * SEQ + r0) >> 7);
    const int ml0 = wm + g, ml1 = ml0 + 8;
#pragma unroll
    for (int nt = 0; nt < 8; ++nt) {
        const int c = h * 64 + nt * 8 + 2 * t;           // even
        uint32_t* tile = g_ot + ((size_t)mblk * 24 + (c >> 5)) * 2176;
        const int kwl = (c & 31) >> 1;
        tile[offh(kwl, ml0)] = pack2(o[nt][0] * inv0, o[nt][1] * inv0);
        tile[offh(kwl, ml1)] = pack2(o[nt][2] * inv1, o[nt][3] * inv1);
    }
}

// =====================================================================
// launch
// =====================================================================
extern "C" void kernel_launch(void* const* d_in, const int* in_sizes, int n_in,
                              void* d_out, int out_size)
{
    (void)in_sizes; (void)n_in; (void)out_size;
    const float* x      = (const float*)d_in[0];
    const float* w_qkv  = (const float*)d_in[1];
    const float* w_proj = (const float*)d_in[2];
    const float* b_proj = (const float*)d_in[3];
    float* out = (float*)d_out;

    cudaFuncSetAttribute((const void*)qkv_mma,
                         cudaFuncAttributeMaxDynamicSharedMemorySize, 104448);
    cudaFuncSetAttribute((const void*)proj_mma,
                         cudaFuncAttributeMaxDynamicSharedMemorySize, 104448);
    cudaFuncSetAttribute((const void*)attn_mma,
                         cudaFuncAttributeMaxDynamicSharedMemorySize, 73728);

    prep_all<<<7296, 256>>>(x, w_qkv, w_proj);
    qkv_mma<<<dim3(18, 64), 256, 104448>>>();
    attn_mma<<<dim3(16, 48), 256, 73728>>>();
    proj_mma<<<dim3(6, 64), 256, 104448>>>(b_proj, out);
}